// round 14
// baseline (speedup 1.0000x reference)
#include <cuda_runtime.h>
#include <cuda_bf16.h>
#include <stdint.h>

// out[B=1024, W=201000] f32 one-hot triple scatter over zeros.
// Inputs: z f32 (unused), hID i32[1024], rID i32[1024], tID i32[1024].
//
// Structure:
//   side stream: cudaMemsetAsync(whole 823MB)  -> 4B memset sets g_flag
//   main stream: concurrent scatter kernel launched at t~0:
//       - computes its target address
//       - pre-walks TLB / warms PTW with a discarded load of that address
//         (scatter touches ~400 distinct 2MB pages; cold uTLB is the prime
//          suspect for the fixed ~7.5us cost of a post-memset scatter)
//       - spins on g_flag (keeps clocks up), then fences and stores 1.0f
//   Critical path: memset (~105us) + flag + ~1us store burst.

#define ENTITIES_N  100000
#define RELATIONS_N 1000
#define WIDTH       201000
#define BATCH       1024
#define NBLK        12
#define THR         256          // 12*256 = 3072 = BATCH*3 threads, 1 store each

__device__ int g_flag;   // set nonzero by CE after the big memset; reset below
__device__ int g_done;   // CTA completion counter for the reset protocol

__global__ void __launch_bounds__(THR) concurrent_scatter(
    const int* __restrict__ hID,
    const int* __restrict__ rID,
    const int* __restrict__ tID,
    float* __restrict__ out)
{
    const unsigned tid = blockIdx.x * (unsigned)THR + threadIdx.x;  // [0,3072)
    const unsigned row = tid / 3u;
    const unsigned j   = tid - row * 3u;

    const int* src = (j == 0) ? hID : (j == 1) ? rID : tID;
    const unsigned off = (j == 0) ? 0u
                       : (j == 1) ? (unsigned)ENTITIES_N
                                  : (unsigned)(ENTITIES_N + RELATIONS_N);

    // Target address (index arrays are input-constant across replays).
    float* addr = out + (size_t)row * WIDTH + off + (unsigned)__ldg(&src[row]);

    // Pre-walk the TLB / warm page tables during the memset window.
    // Volatile load, value discarded (reads poison/zeros — never used).
    unsigned dummy;
    asm volatile("ld.global.cg.u32 %0, [%1];" : "=r"(dummy) : "l"(addr));

    // Wait for the CE fill to complete (flag set after the big memset).
    volatile int* flag = &g_flag;
    while (*flag == 0) { }
    __threadfence();   // order our 1.0 stores after the observed flag

    *addr = 1.0f;

    // Reset protocol so the graph replays deterministically.
    __syncthreads();
    if (threadIdx.x == 0) {
        const int old = atomicAdd(&g_done, 1);
        if (old == NBLK - 1) {   // last CTA out resets both flags
            g_flag = 0;
            g_done = 0;
        }
    }
}

extern "C" void kernel_launch(void* const* d_in, const int* in_sizes, int n_in,
                              void* d_out, int out_size) {
    const int* hID = (const int*)d_in[1];
    const int* rID = (const int*)d_in[2];
    const int* tID = (const int*)d_in[3];
    float* out = (float*)d_out;

    static cudaStream_t side = nullptr;
    static cudaEvent_t evFork = nullptr, evJoin = nullptr;
    static void* flag_addr = nullptr;
    if (!side) {
        cudaStreamCreateWithFlags(&side, cudaStreamNonBlocking);
        cudaEventCreateWithFlags(&evFork, cudaEventDisableTiming);
        cudaEventCreateWithFlags(&evJoin, cudaEventDisableTiming);
        cudaGetSymbolAddress(&flag_addr, g_flag);
    }

    // Fork the CE branch: big fill, then set the flag (stream-ordered).
    cudaEventRecord(evFork, 0);
    cudaStreamWaitEvent(side, evFork, 0);
    cudaMemsetAsync(out, 0, (size_t)out_size * sizeof(float), side);
    cudaMemsetAsync(flag_addr, 1, sizeof(int), side);   // g_flag = 0x01010101
    cudaEventRecord(evJoin, side);

    // Main stream: scatter kernel runs concurrently with the memset.
    concurrent_scatter<<<NBLK, THR>>>(hID, rID, tID, out);

    // Join the CE branch (kernel already self-synchronizes via the flag).
    cudaStreamWaitEvent(0, evJoin, 0);
}

// round 15
// speedup vs baseline: 1.0181x; 1.0181x over previous
#include <cuda_runtime.h>
#include <cuda_bf16.h>
#include <stdint.h>

// out[B=1024, W=201000] f32 one-hot triple scatter over zeros.
// Inputs: z f32 (unused), hID i32[1024], rID i32[1024], tID i32[1024].
//
// Structure (single stream, two nodes):
//   node A: cudaMemsetAsync rows [0,896)   — CE fill path, ~7.9 TB/s, ~91us
//   node B: big SM kernel:
//             - fills rows [896,1024) (103MB, 5025 blocks — enough work to
//               amortize the post-CE launch/clock-ramp cost that killed every
//               tiny scatter kernel at ~7.5us)
//             - scatters region-B ones via per-thread chunk ownership
//             - scatters region-A ones from 21 dedicated tail blocks
//               (stream order guarantees memset A completed)

#define ENTITIES_N  100000
#define RELATIONS_N 1000
#define WIDTH       201000
#define BATCH       1024
#define ROWS_A      896
#define ROWS_B      128
#define W8          25125u                    // v8 chunks per row
#define B_V8        (ROWS_B * W8)             // 3,216,000
#define THREADS     128
#define V8_PER_THR  5
#define V8_PER_BLK  (THREADS * V8_PER_THR)    // 640
#define FILL_BLOCKS (B_V8 / V8_PER_BLK)       // 5025 exact
#define SCAT_BLOCKS 21                        // 21*128 = 2688 = ROWS_A*3
#define GRID        (FILL_BLOCKS + SCAT_BLOCKS)

__global__ void __launch_bounds__(THREADS) tail_fill_scatter(
    const int* __restrict__ hID,
    const int* __restrict__ rID,
    const int* __restrict__ tID,
    float* __restrict__ out)
{
    if (blockIdx.x < FILL_BLOCKS) {
        // ---- Fill region B (rows [896,1024)) with zeros, 5 x v8 stores ----
        float* outB = out + (size_t)ROWS_A * WIDTH;
        const unsigned base = blockIdx.x * (unsigned)V8_PER_BLK + threadIdx.x;
#pragma unroll
        for (int k = 0; k < V8_PER_THR; k++) {
            float* addr = outB + (size_t)(base + k * THREADS) * 8;
            asm volatile(
                "st.global.v8.f32 [%0], {%1,%1,%1,%1,%1,%1,%1,%1};"
                :: "l"(addr), "f"(0.0f) : "memory");
        }

        // ---- Region-B hot elements owned by this thread ----
        const unsigned rowLo = base / W8;
        const unsigned rowHi = (base + (V8_PER_THR - 1) * THREADS) / W8;
#pragma unroll
        for (int which = 0; which < 2; which++) {
            const unsigned rrel = which ? rowHi : rowLo;
            if (which && rowHi == rowLo) break;
            const unsigned grow = rrel + ROWS_A;
            const unsigned rbase = rrel * (unsigned)WIDTH;
            unsigned q[3];
            q[0] = rbase + (unsigned)__ldg(&hID[grow]);
            q[1] = rbase + (unsigned)(ENTITIES_N + __ldg(&rID[grow]));
            q[2] = rbase + (unsigned)(ENTITIES_N + RELATIONS_N + __ldg(&tID[grow]));
#pragma unroll
            for (int j = 0; j < 3; j++) {
                const unsigned chunk = q[j] >> 3;
                const unsigned d = chunk - base;      // unsigned wrap ok
                if (d < (unsigned)V8_PER_BLK && (d & (THREADS - 1)) == 0u)
                    outB[q[j]] = 1.0f;                // same-thread order
            }
        }
    } else {
        // ---- Scatter region-A ones (memset A completed: stream order) ----
        const unsigned t = (blockIdx.x - FILL_BLOCKS) * (unsigned)THREADS +
                           threadIdx.x;              // [0, 2688)
        const unsigned row = t / 3u;
        const unsigned j   = t - row * 3u;
        const int* src = (j == 0) ? hID : (j == 1) ? rID : tID;
        const unsigned off = (j == 0) ? 0u
                           : (j == 1) ? (unsigned)ENTITIES_N
                                      : (unsigned)(ENTITIES_N + RELATIONS_N);
        out[(size_t)row * WIDTH + off + (unsigned)__ldg(&src[row])] = 1.0f;
    }
}

extern "C" void kernel_launch(void* const* d_in, const int* in_sizes, int n_in,
                              void* d_out, int out_size) {
    const int* hID = (const int*)d_in[1];
    const int* rID = (const int*)d_in[2];
    const int* tID = (const int*)d_in[3];
    float* out = (float*)d_out;

    // CE fills rows [0, 896).
    cudaMemsetAsync(out, 0, (size_t)ROWS_A * WIDTH * sizeof(float), 0);

    // One big SM kernel: fill the tail region + full scatter.
    tail_fill_scatter<<<GRID, THREADS>>>(hID, rID, tID, out);
}